// round 3
// baseline (speedup 1.0000x reference)
#include <cuda_runtime.h>

// ---------------------------------------------------------------------------
// SSIM (16,3,512,512) fp32, 11x11 Gaussian (sigma=1.5), zero pad, global mean.
// Separable conv; horizontal 11-tap from SMEM staged padded rows; vertical
// 11-tap via STATIC ring (phases unrolled mod 11 => no register shifts).
// Distance-2 LDG prefetch, double-buffered SMEM, one barrier per row.
// Single kernel: last-finishing CTA does the (deterministic) final reduction.
// ---------------------------------------------------------------------------

#define IMW     512
#define IMH     512
#define NT      512                 // one thread per column
#define TH      171                 // output rows per band (3 bands cover 512)
#define NBANDS  3
#define NPLANES 48                  // 16 * 3
#define NBLOCKS (NPLANES * NBANDS)  // 144 CTAs -> single wave on 148 SMs
#define SSIM_C1 0.0001f
#define SSIM_C2 0.0009f

__device__ float        g_partials[NBLOCKS];
__device__ unsigned int g_count;    // static-zero; reset by last block each run

// One row-phase. P must be a compile-time constant (= ir mod 11).
// PROLOG=true limits ring taps to d <= P (rows 0..10 only).
#define PHASE(P, IRV, PROLOG) do {                                            \
    const int ir_ = (IRV);                                                    \
    if (ir_ + 2 < nrows) LOADR(ir_ + 2, (ir_) & 1);                           \
    {                                                                         \
        const float* xr = sx[(ir_) & 1];                                      \
        const float* yr = sy[(ir_) & 1];                                      \
        float hx = 0.f, hy = 0.f, hxx = 0.f, hyy = 0.f, hxy = 0.f;            \
        _Pragma("unroll")                                                     \
        for (int k = 0; k < 11; ++k) {                                        \
            const float xv = xr[t + k];                                       \
            const float yv = yr[t + k];                                       \
            hx  += W[k] * xv;                                                 \
            hy  += W[k] * yv;                                                 \
            hxx += W[k] * (xv * xv);                                          \
            hyy += W[k] * (yv * yv);                                          \
            hxy += W[k] * (xv * yv);                                          \
        }                                                                     \
        _Pragma("unroll")                                                     \
        for (int s = 0; s < 11; ++s) {                                        \
            const int d = ((P) - s + 11) % 11;  /* compile-time */            \
            if (!(PROLOG) || d <= (P)) {                                      \
                const float wd = W[d];                                        \
                A0[s] += wd * hx;  A1[s] += wd * hy;                          \
                A2[s] += wd * hxx; A3[s] += wd * hyy; A4[s] += wd * hxy;      \
            }                                                                 \
        }                                                                     \
        if (ir_ >= 10) {            /* output row o = ir-10 complete */       \
            const int e = ((P) + 1) % 11;       /* compile-time */            \
            const float mu1 = A0[e], mu2 = A1[e];                             \
            const float m11 = mu1 * mu1;                                      \
            const float m22 = mu2 * mu2;                                      \
            const float m12 = mu1 * mu2;                                      \
            const float s1  = A2[e] - m11;                                    \
            const float s2  = A3[e] - m22;                                    \
            const float s12 = A4[e] - m12;                                    \
            const float num = (2.f * m12 + SSIM_C1) * (2.f * s12 + SSIM_C2);  \
            const float den = (m11 + m22 + SSIM_C1) * (s1 + s2 + SSIM_C2);    \
            ssum += __fdividef(num, den);                                     \
            A0[e] = 0.f; A1[e] = 0.f; A2[e] = 0.f; A3[e] = 0.f; A4[e] = 0.f;  \
        }                                                                     \
        if (ir_ + 1 < nrows) STAGER((ir_ + 1) & 1, (ir_ + 1) & 1);            \
        __syncthreads();                                                      \
    }                                                                         \
} while (0)

__global__ void __launch_bounds__(NT, 1)
ssim_main(const float* __restrict__ img1, const float* __restrict__ img2,
          float* __restrict__ out)
{
    // Normalized 1D Gaussian, sigma=1.5, 11 taps (compile-time immediates)
    const float W[11] = {
        0.00102838f, 0.00759874f, 0.03600077f, 0.10936069f, 0.21300553f,
        0.26601180f,
        0.21300553f, 0.10936069f, 0.03600077f, 0.00759874f, 0.00102838f
    };

    const int band  = blockIdx.x;           // 0..2
    const int plane = blockIdx.y;           // 0..47
    const int t     = threadIdx.x;          // column 0..511
    const int r0    = band * TH;
    const int rows  = (IMH - r0 < TH) ? (IMH - r0) : TH;   // 171/171/170
    const int nrows = rows + 10;
    const int pbase = plane * (IMW * IMH);

    // Double-buffered padded rows: staged slot j in [0,522) <-> image col j-5.
    // Row r is always staged in buffer (r & 1) from register set (r & 1).
    __shared__ float sx[2][522];
    __shared__ float sy[2][522];

    // Static ring: slot s holds partials for output rows o with o % 11 == s.
    float A0[11], A1[11], A2[11], A3[11], A4[11];
#pragma unroll
    for (int j = 0; j < 11; ++j) {
        A0[j] = 0.f; A1[j] = 0.f; A2[j] = 0.f; A3[j] = 0.f; A4[j] = 0.f;
    }

    const int  cmain = t - 5;               // staged slot t     <-> col t-5
    const bool mok   = (t >= 5);
    const bool tok   = (t < 5);              // staged slot 512+t <-> col 507+t

    float px0[2], py0[2], px1[2], py1[2];    // prefetch sets, parity = row & 1

    auto LOADR = [&](int ir, int s) {
        const int gr = r0 - 5 + ir;          // global row (zero pad if OOB)
        float a = 0.f, b = 0.f, c = 0.f, d = 0.f;
        if ((unsigned)gr < (unsigned)IMH) {
            const float* p1 = img1 + pbase + gr * IMW;
            const float* p2 = img2 + pbase + gr * IMW;
            if (mok) { a = __ldg(p1 + cmain);   b = __ldg(p2 + cmain); }
            if (tok) { c = __ldg(p1 + 507 + t); d = __ldg(p2 + 507 + t); }
        }
        px0[s] = a; py0[s] = b; px1[s] = c; py1[s] = d;
    };
    auto STAGER = [&](int s, int b) {
        sx[b][t] = px0[s];  sy[b][t] = py0[s];
        if (t < 10) { sx[b][512 + t] = px1[s]; sy[b][512 + t] = py1[s]; }
    };

    // Prologue: rows 0,1 in flight; row 0 staged.
    LOADR(0, 0);
    LOADR(1, 1);
    STAGER(0, 0);
    __syncthreads();

    float ssum = 0.f;

    // Rows 0..10: fully unrolled prologue (restricted ring taps d <= p).
#pragma unroll
    for (int p = 0; p <= 10; ++p) {
        PHASE(p, p, true);
    }

    // Steady state: base is a multiple of 11, so (base+q) % 11 == q.
    for (int base = 11; base < nrows; base += 11) {
#pragma unroll
        for (int q = 0; q < 11; ++q) {
            const int ir = base + q;
            if (ir < nrows) {               // uniform across block
                PHASE(q, ir, false);
            }
        }
    }

    // ---- deterministic block reduction ----
    const int lane = t & 31;
    const int wid  = t >> 5;
#pragma unroll
    for (int off = 16; off; off >>= 1)
        ssum += __shfl_xor_sync(0xffffffffu, ssum, off);

    __shared__ float wsum[16];
    __shared__ bool  islast;
    if (lane == 0) wsum[wid] = ssum;
    __syncthreads();
    if (t == 0) {
        float v = 0.f;
#pragma unroll
        for (int i = 0; i < 16; ++i) v += wsum[i];
        g_partials[plane * NBANDS + band] = v;
        __threadfence();
        const unsigned n = atomicAdd(&g_count, 1u);
        islast = (n == (unsigned)(NBLOCKS - 1));
    }
    __syncthreads();

    // ---- last CTA: fixed-order (deterministic) final reduction ----
    if (islast) {
        __threadfence();
        float v = (t < NBLOCKS) ? g_partials[t] : 0.f;
#pragma unroll
        for (int off = 16; off; off >>= 1)
            v += __shfl_xor_sync(0xffffffffu, v, off);
        if (lane == 0) wsum[wid] = v;
        __syncthreads();
        if (t == 0) {
            float s = 0.f;
#pragma unroll
            for (int i = 0; i < 16; ++i) s += wsum[i];
            out[0] = s * (1.0f / 12582912.0f);  // / (16*3*512*512)
            g_count = 0u;                        // reset for next graph replay
        }
    }
}

extern "C" void kernel_launch(void* const* d_in, const int* in_sizes, int n_in,
                              void* d_out, int out_size)
{
    const float* img1 = (const float*)d_in[0];
    const float* img2 = (const float*)d_in[1];
    (void)in_sizes; (void)n_in; (void)out_size;

    dim3 grid(NBANDS, NPLANES);
    ssim_main<<<grid, NT>>>(img1, img2, (float*)d_out);
}

// round 4
// speedup vs baseline: 1.1643x; 1.1643x over previous
#include <cuda_runtime.h>

// ---------------------------------------------------------------------------
// SSIM (16,3,512,512) fp32, 11x11 Gaussian (sigma=1.5), zero pad, global mean.
// Separable conv; horizontal 11-tap from WARP-PRIVATE SMEM halo segments
// (no __syncthreads in the main loop, only __syncwarp); vertical 11-tap via
// static mod-11 register ring (zero shifts). float2-interleaved staging
// (LDS.64). Uniform phases (no prologue): full taps + unconditional slot
// reset make pre-window garbage provably self-cleaning.
// ---------------------------------------------------------------------------

#define IMW     512
#define IMH     512
#define NT      512                 // one thread per column
#define TH      171                 // output rows per band (3 bands cover 512)
#define NBANDS  3
#define NPLANES 48                  // 16 * 3
#define NBLOCKS (NPLANES * NBANDS)  // 144 CTAs -> single wave
#define SSIM_C1 0.0001f
#define SSIM_C2 0.0009f

__device__ float        g_partials[NBLOCKS];
__device__ unsigned int g_count;    // zero-init; reset by last block each run

// One row-phase. P must be a compile-time constant == ir mod 11.
#define PHASE(P, IRV) do {                                                    \
    const int ir_ = (IRV);                                                    \
    if (ir_ < nrows) {                                                        \
        if (ir_ + 2 < nrows) LOADR(ir_ + 2, (ir_) & 1);                       \
        {                                                                     \
            const float2* sp = &seg[(ir_) & 1][w][l];                         \
            float hx = 0.f, hy = 0.f, hxx = 0.f, hyy = 0.f, hxy = 0.f;        \
            _Pragma("unroll")                                                 \
            for (int k = 0; k < 11; ++k) {                                    \
                const float2 v = sp[k];                                       \
                hx  += W[k] * v.x;                                            \
                hy  += W[k] * v.y;                                            \
                hxx += W[k] * (v.x * v.x);                                    \
                hyy += W[k] * (v.y * v.y);                                    \
                hxy += W[k] * (v.x * v.y);                                    \
            }                                                                 \
            _Pragma("unroll")                                                 \
            for (int s = 0; s < 11; ++s) {                                    \
                const int d = ((P) - s + 11) % 11;  /* compile-time */        \
                const float wd = W[d];                                        \
                A0[s] += wd * hx;  A1[s] += wd * hy;                          \
                A2[s] += wd * hxx; A3[s] += wd * hyy; A4[s] += wd * hxy;      \
            }                                                                 \
            const int e_ = ((P) + 1) % 11;          /* compile-time */        \
            if (ir_ >= 10) {        /* output row m = ir-10 is real */        \
                const float mu1 = A0[e_], mu2 = A1[e_];                       \
                const float m11 = mu1 * mu1;                                  \
                const float m22 = mu2 * mu2;                                  \
                const float m12 = mu1 * mu2;                                  \
                const float s1  = A2[e_] - m11;                               \
                const float s2  = A3[e_] - m22;                               \
                const float s12 = A4[e_] - m12;                               \
                const float num = (2.f*m12 + SSIM_C1) * (2.f*s12 + SSIM_C2);  \
                const float den = (m11 + m22 + SSIM_C1) * (s1 + s2 + SSIM_C2);\
                ssum += __fdividef(num, den);                                 \
            }                                                                 \
            A0[e_] = 0.f; A1[e_] = 0.f; A2[e_] = 0.f;                         \
            A3[e_] = 0.f; A4[e_] = 0.f;                                       \
            if (ir_ + 1 < nrows) STAGER((ir_ + 1) & 1, (ir_ + 1) & 1);        \
            __syncwarp();                                                     \
        }                                                                     \
    }                                                                         \
} while (0)

__global__ void __launch_bounds__(NT, 1)
ssim_main(const float* __restrict__ img1, const float* __restrict__ img2,
          float* __restrict__ out)
{
    // Normalized 1D Gaussian, sigma=1.5, 11 taps (compile-time immediates)
    const float W[11] = {
        0.00102838f, 0.00759874f, 0.03600077f, 0.10936069f, 0.21300553f,
        0.26601180f,
        0.21300553f, 0.10936069f, 0.03600077f, 0.00759874f, 0.00102838f
    };

    const int band  = blockIdx.x;           // 0..2
    const int plane = blockIdx.y;           // 0..47
    const int t     = threadIdx.x;          // column 0..511
    const int l     = t & 31;               // lane
    const int w     = t >> 5;               // warp
    const int r0    = band * TH;
    const int rows  = (IMH - r0 < TH) ? (IMH - r0) : TH;   // 171/171/170
    const int nrows = rows + 10;
    const int pbase = plane * (IMW * IMH);

    // Warp-private double-buffered halo segments.
    // seg[buf][w][j], j in [0,42): (x,y) of image column 32*w - 5 + j.
    __shared__ float2 seg[2][16][44];

    // Static ring: slot s holds partials for output rows m with m % 11 == s.
    float A0[11], A1[11], A2[11], A3[11], A4[11];
#pragma unroll
    for (int j = 0; j < 11; ++j) {
        A0[j] = 0.f; A1[j] = 0.f; A2[j] = 0.f; A3[j] = 0.f; A4[j] = 0.f;
    }

    // Column mapping (identical for every row):
    //   staged j = l      <-> col t - 5   (valid iff t >= 5)
    //   staged j = 32 + l <-> col t + 27  (staged iff l < 10, valid iff < 512)
    const int  c1   = t - 5;
    const bool c1ok = (t >= 5);
    const int  c2   = t + 27;
    const bool c2st = (l < 10);
    const bool c2ok = c2st && (c2 < IMW);

    float px0[2], py0[2], px1[2], py1[2];    // prefetch regs, parity = row & 1

    auto LOADR = [&](int ir, int s) {
        const int gr = r0 - 5 + ir;          // global row (zero pad if OOB)
        float a = 0.f, b = 0.f, c = 0.f, d = 0.f;
        if ((unsigned)gr < (unsigned)IMH) {
            const float* p1 = img1 + pbase + gr * IMW;
            const float* p2 = img2 + pbase + gr * IMW;
            if (c1ok) { a = __ldg(p1 + c1); b = __ldg(p2 + c1); }
            if (c2ok) { c = __ldg(p1 + c2); d = __ldg(p2 + c2); }
        }
        px0[s] = a; py0[s] = b; px1[s] = c; py1[s] = d;
    };
    auto STAGER = [&](int s, int b) {
        seg[b][w][l] = make_float2(px0[s], py0[s]);
        if (c2st) seg[b][w][32 + l] = make_float2(px1[s], py1[s]);
    };

    // Prologue: rows 0,1 in flight; row 0 staged. (row r lives in set r & 1)
    LOADR(0, 0);
    LOADR(1, 1);
    STAGER(0, 0);
    __syncwarp();

    float ssum = 0.f;

    // Uniform phases; base multiple of 11 so (base+q) % 11 == q.
    for (int base = 0; base < nrows; base += 11) {
#pragma unroll
        for (int q = 0; q < 11; ++q) {
            PHASE(q, base + q);
        }
    }

    // ---- deterministic block reduction ----
    __syncthreads();
#pragma unroll
    for (int off = 16; off; off >>= 1)
        ssum += __shfl_xor_sync(0xffffffffu, ssum, off);

    __shared__ float wsum[16];
    __shared__ bool  islast;
    if (l == 0) wsum[w] = ssum;
    __syncthreads();
    if (t == 0) {
        float v = 0.f;
#pragma unroll
        for (int i = 0; i < 16; ++i) v += wsum[i];
        g_partials[plane * NBANDS + band] = v;
        __threadfence();
        const unsigned n = atomicAdd(&g_count, 1u);
        islast = (n == (unsigned)(NBLOCKS - 1));
    }
    __syncthreads();

    // ---- last CTA: fixed-order (deterministic) final reduction ----
    if (islast) {
        __threadfence();
        float v = (t < NBLOCKS) ? g_partials[t] : 0.f;
#pragma unroll
        for (int off = 16; off; off >>= 1)
            v += __shfl_xor_sync(0xffffffffu, v, off);
        if (l == 0) wsum[w] = v;
        __syncthreads();
        if (t == 0) {
            float s = 0.f;
#pragma unroll
            for (int i = 0; i < 16; ++i) s += wsum[i];
            out[0] = s * (1.0f / 12582912.0f);  // / (16*3*512*512)
            g_count = 0u;                        // reset for next graph replay
        }
    }
}

extern "C" void kernel_launch(void* const* d_in, const int* in_sizes, int n_in,
                              void* d_out, int out_size)
{
    const float* img1 = (const float*)d_in[0];
    const float* img2 = (const float*)d_in[1];
    (void)in_sizes; (void)n_in; (void)out_size;

    dim3 grid(NBANDS, NPLANES);
    ssim_main<<<grid, NT>>>(img1, img2, (float*)d_out);
}